// round 15
// baseline (speedup 1.0000x reference)
#include <cuda_runtime.h>
#include <cuda_fp16.h>
#include <cstdint>

// Problem constants
#define NB   64            // batch
#define CC   128           // channels
#define TT   300           // time
#define VV   25            // vertices
#define KK   3             // adjacency count
#define TV   (TT*VV)       // 7500 rows per n (r = t*25+w)
#define KD   (KK*CC)       // 384 = main GEMM K-dim
#define NELEM (NB*CC*TT*VV) // 61,440,000 output elems
#define BN_EPS 1e-5f
#define RPAD 7552          // padded rows per n for g_z (59*128)
#define XS 40              // zgemm sX row stride (fp16)
#define SS 136             // zgemm stage row stride (fp16)
#define MBLK 59            // mgemm row-blocks per n
#define NBLK2 (MBLK*NB)    // 3776 stats partials
#define KH 64              // mgemm half-chunk K size
#define KPH 72             // mgemm smem row stride (halfs)

typedef unsigned long long u64;

// ---------------- fp16 mma.sync + cp.async (base PTX, plain sm_103) ---------
__device__ __forceinline__ void mma16816(float* c, const uint32_t* a, const uint32_t* b) {
    asm volatile(
        "mma.sync.aligned.m16n8k16.row.col.f32.f16.f16.f32 "
        "{%0,%1,%2,%3}, {%4,%5,%6,%7}, {%8,%9}, {%0,%1,%2,%3};"
        : "+f"(c[0]), "+f"(c[1]), "+f"(c[2]), "+f"(c[3])
        : "r"(a[0]), "r"(a[1]), "r"(a[2]), "r"(a[3]), "r"(b[0]), "r"(b[1]));
}
__device__ __forceinline__ uint32_t smem_u32(const void* p) {
    uint32_t a;
    asm("{ .reg .u64 t; cvta.to.shared.u64 t, %1; cvt.u32.u64 %0, t; }"
        : "=r"(a) : "l"(p));
    return a;
}
__device__ __forceinline__ void cpa16(uint32_t s, const void* g) {
    asm volatile("cp.async.cg.shared.global [%0], [%1], 16;" :: "r"(s), "l"(g));
}
#define CP_COMMIT() asm volatile("cp.async.commit_group;" ::: "memory")
#define CP_WAIT(N)  asm volatile("cp.async.wait_group %0;" :: "n"(N) : "memory")

// ---------------- scratch ----------------------------------------------------
__device__ __half g_z[(size_t)NB * RPAD * KD];   // z[n][r][(k,ci)] fp16
__device__ __half g_W2[CC * KD];                 // W2[c][(k,ci)] fp16
__device__ float g_bias2[CC * VV];               // bias folded through A
__device__ float g_psum[NBLK2 * CC];
__device__ float g_psq[NBLK2 * CC];
__device__ float g_scale[CC];
__device__ float g_shift[CC];

// ---------------- kernel -1: dummy (keeps ncu's profiled slot on mgemm) -----
__global__ void dummy_kernel() {}

// ---------------- kernel 0: prep (W2 fp16 permuted, fold bias) --------------
__global__ void prep_kernel(const float* __restrict__ W,
                            const float* __restrict__ b,
                            const float* __restrict__ A) {
    int tid = blockIdx.x * blockDim.x + threadIdx.x;
    int stride = gridDim.x * blockDim.x;
    for (int i = tid; i < CC * KD; i += stride) {
        int c = i / KD, rem = i - c * KD;
        int k = rem >> 7, ci = rem & 127;
        g_W2[i] = __float2half(W[(k * CC + c) * CC + ci]);
    }
    for (int i = tid; i < CC * VV; i += stride) {
        int c = i / VV, w = i % VV;
        float s = 0.f;
        #pragma unroll
        for (int k = 0; k < KK; k++) {
            float cs = 0.f;
            #pragma unroll
            for (int v = 0; v < VV; v++) cs += A[k * VV * VV + v * VV + w];
            s += b[k * CC + c] * cs;
        }
        g_bias2[i] = s;
    }
}

// ---------------- kernel 1: z-GEMM (unchanged from R14) ----------------------
__global__ void __launch_bounds__(256) zgemm_kernel(const float* __restrict__ x,
                                                    const float* __restrict__ A) {
    __shared__ __half sX[128 * XS];       // [ci][v] padded
    __shared__ __half sBA[96 * XS];       // [(k*25+w)][v] padded, A transposed
    __shared__ __half stage[96 * SS];     // [(k,w)][ci]

    const int tb = blockIdx.x, n = blockIdx.y;
    const int tid = threadIdx.x;
    const int wid = tid >> 5, lane = tid & 31;
    const int wm = wid & 3, wn = wid >> 2;
    const int lr = lane >> 2, kq = (lane & 3) * 2;
    const float* xn0 = x + (size_t)(n * CC) * TV;

    for (int e = tid; e < 128 * XS; e += 256) sX[e] = __float2half(0.f);
    for (int e = tid; e < 96 * XS; e += 256) sBA[e] = __float2half(0.f);
    __syncthreads();
    for (int e = tid; e < KK * VV * VV; e += 256) {
        int k = e / (VV * VV), rem = e - k * VV * VV;
        int v = rem / VV, w = rem - v * VV;
        sBA[(k * VV + w) * XS + v] = __float2half(A[e]);
    }
    {
        const float* xn = xn0 + (tb * 10) * VV;
        for (int e = tid; e < CC * VV; e += 256)
            sX[(e / VV) * XS + e % VV] = __float2half(xn[(size_t)(e / VV) * TV + e % VV]);
    }
    __syncthreads();

    for (int tt = 0; tt < 10; tt++) {
        const int t = tb * 10 + tt;

        float acc[2][6][4];
        #pragma unroll
        for (int mt = 0; mt < 2; mt++)
            #pragma unroll
            for (int nt = 0; nt < 6; nt++)
                #pragma unroll
                for (int j = 0; j < 4; j++) acc[mt][nt][j] = 0.f;

        #pragma unroll
        for (int kk = 0; kk < 2; kk++) {
            const int k0 = kk * 16 + kq;
            uint32_t af[2][4], bf[6][2];
            #pragma unroll
            for (int mt = 0; mt < 2; mt++) {
                int rm = wm * 32 + mt * 16 + lr;
                af[mt][0] = *(const uint32_t*)(sX + rm * XS + k0);
                af[mt][1] = *(const uint32_t*)(sX + (rm + 8) * XS + k0);
                af[mt][2] = *(const uint32_t*)(sX + rm * XS + k0 + 8);
                af[mt][3] = *(const uint32_t*)(sX + (rm + 8) * XS + k0 + 8);
            }
            #pragma unroll
            for (int nt = 0; nt < 6; nt++) {
                int rn = wn * 48 + nt * 8 + lr;
                bf[nt][0] = *(const uint32_t*)(sBA + rn * XS + k0);
                bf[nt][1] = *(const uint32_t*)(sBA + rn * XS + k0 + 8);
            }
            #pragma unroll
            for (int mt = 0; mt < 2; mt++)
                #pragma unroll
                for (int nt = 0; nt < 6; nt++)
                    mma16816(acc[mt][nt], af[mt], bf[nt]);
        }

        #pragma unroll
        for (int mt = 0; mt < 2; mt++) {
            int row = wm * 32 + mt * 16 + lr;
            #pragma unroll
            for (int nt = 0; nt < 6; nt++) {
                int col = wn * 48 + nt * 8 + kq;
                stage[col * SS + row]           = __float2half(acc[mt][nt][0]);
                stage[(col + 1) * SS + row]     = __float2half(acc[mt][nt][1]);
                stage[col * SS + row + 8]       = __float2half(acc[mt][nt][2]);
                stage[(col + 1) * SS + row + 8] = __float2half(acc[mt][nt][3]);
            }
        }
        __syncthreads();

        __half* zb = g_z + ((size_t)n * RPAD + t * VV) * KD;
        for (int e = tid; e < 75 * 16; e += 256) {
            int q = e >> 4, h8 = (e & 15);
            int k = q / VV, w = q - k * VV;
            *(uint4*)(zb + (size_t)w * KD + k * CC + h8 * 8) =
                *(const uint4*)(stage + q * SS + h8 * 8);
        }
        if (tt < 9) {
            const float* xn = xn0 + (t + 1) * VV;
            for (int e = tid; e < CC * VV; e += 256)
                sX[(e / VV) * XS + e % VV] = __float2half(xn[(size_t)(e / VV) * TV + e % VV]);
        }
        __syncthreads();
    }
}

// ---------------- kernel 2: main GEMM, 2-stage cp.async pipeline ------------
// K split into 6 half-chunks of 64; sA/sB double-buffered. regs (122) bind
// occupancy at 2 CTA/SM, so the extra smem is free.
#define SMEM_SA(buf) ((buf) * 18432)
#define SMEM_SB(buf) (36864 + (buf) * 18432)
#define SMEM_SCR 73728
#define SMEM_M_TOTAL (73728 + 2048)

__global__ void __launch_bounds__(256) mgemm_kernel(const float* __restrict__ x,
                                                    float* __restrict__ out) {
    extern __shared__ char sm[];
    float* out_s = (float*)sm;                  // [128 c][130] epilogue alias
    float* scr = (float*)(sm + SMEM_SCR);       // 512 floats

    const int r0 = blockIdx.x * 128;
    const int n  = blockIdx.y;
    const int tid = threadIdx.x;
    const int wid = tid >> 5, lane = tid & 31;
    const int wm = wid & 1, wn = wid >> 1;
    const int lr = lane >> 2, kq = (lane & 3) * 2;
    const int crow = tid >> 3, cc8 = (tid & 7) * 8;   // stage-copy coords (1024 chunks)

    const __half* srcAbase = g_z + ((size_t)n * RPAD + r0) * KD;
    const uint32_t smbase = smem_u32(sm);

    // issue one stage: 128 rows x 64 halfs for sA and sB
    auto issue_stage = [&](int ch, int buf) {
        const __half* srcA = srcAbase + ch * KH;
        const __half* srcB = g_W2 + ch * KH;
        uint32_t dA = smbase + SMEM_SA(buf) + (crow * KPH + cc8) * 2;
        uint32_t dB = smbase + SMEM_SB(buf) + (crow * KPH + cc8) * 2;
        #pragma unroll
        for (int i = 0; i < 4; i++) {
            int row = crow + i * 32;
            cpa16(dA + i * 32 * KPH * 2, srcA + (size_t)row * KD + cc8);
            cpa16(dB + i * 32 * KPH * 2, srcB + (size_t)row * KD + cc8);
        }
        CP_COMMIT();
    };

    issue_stage(0, 0);

    float acc[4][4][4];
    #pragma unroll
    for (int mt = 0; mt < 4; mt++)
        #pragma unroll
        for (int nt = 0; nt < 4; nt++)
            #pragma unroll
            for (int j = 0; j < 4; j++) acc[mt][nt][j] = 0.f;

    #pragma unroll
    for (int ch = 0; ch < 6; ch++) {
        if (ch < 5) issue_stage(ch + 1, (ch + 1) & 1);
        if (ch < 5) { CP_WAIT(1); } else { CP_WAIT(0); }
        __syncthreads();

        const __half* sA = (const __half*)(sm + SMEM_SA(ch & 1));
        const __half* sB = (const __half*)(sm + SMEM_SB(ch & 1));
        #pragma unroll
        for (int kk = 0; kk < 4; kk++) {
            const int k0 = kk * 16 + kq;
            uint32_t af[4][4], bf[4][2];
            #pragma unroll
            for (int mt = 0; mt < 4; mt++) {
                int rm = wm * 64 + mt * 16 + lr;
                af[mt][0] = *(const uint32_t*)(sA + rm * KPH + k0);
                af[mt][1] = *(const uint32_t*)(sA + (rm + 8) * KPH + k0);
                af[mt][2] = *(const uint32_t*)(sA + rm * KPH + k0 + 8);
                af[mt][3] = *(const uint32_t*)(sA + (rm + 8) * KPH + k0 + 8);
            }
            #pragma unroll
            for (int nt = 0; nt < 4; nt++) {
                int rn = wn * 32 + nt * 8 + lr;
                bf[nt][0] = *(const uint32_t*)(sB + rn * KPH + k0);
                bf[nt][1] = *(const uint32_t*)(sB + rn * KPH + k0 + 8);
            }
            #pragma unroll
            for (int mt = 0; mt < 4; mt++)
                #pragma unroll
                for (int nt = 0; nt < 4; nt++)
                    mma16816(acc[mt][nt], af[mt], bf[nt]);
        }
        __syncthreads();   // all warps done with this buffer before it's refilled
    }

    // stage D: out_s[c][r_loc]  (aliases pipeline buffers)
    #pragma unroll
    for (int mt = 0; mt < 4; mt++) {
        int r_loc = wm * 64 + mt * 16 + lr;
        #pragma unroll
        for (int nt = 0; nt < 4; nt++) {
            int cb = wn * 32 + nt * 8 + kq;
            out_s[cb * 130 + r_loc]           = acc[mt][nt][0];
            out_s[(cb + 1) * 130 + r_loc]     = acc[mt][nt][1];
            out_s[cb * 130 + r_loc + 8]       = acc[mt][nt][2];
            out_s[(cb + 1) * 130 + r_loc + 8] = acc[mt][nt][3];
        }
    }
    __syncthreads();

    // Phase A: bias + residual + relu; write out; keep in smem for stats
    for (int e = tid; e < 128 * 128; e += 256) {
        int c = e >> 7, r = e & 127;
        int gr = r0 + r;
        if (gr < TV) {
            size_t gidx = (size_t)(n * CC + c) * TV + gr;
            float v = out_s[c * 130 + r] + g_bias2[c * VV + gr % VV] + x[gidx];
            v = fmaxf(v, 0.f);
            out_s[c * 130 + r] = v;
            out[gidx] = v;
        }
    }
    __syncthreads();

    // Phase B: per-channel stats partials
    const int cc = tid & 127, th = tid >> 7;
    const int rmax = (TV - r0 < 128) ? (TV - r0) : 128;
    float bs = 0.f, bq = 0.f;
    for (int r = th; r < rmax; r += 2) {
        float v = out_s[cc * 130 + r];
        bs += v; bq += v * v;
    }
    scr[tid] = bs; scr[256 + tid] = bq;
    __syncthreads();
    if (th == 0) {
        int p = (n * MBLK + blockIdx.x) * CC + cc;
        g_psum[p] = scr[cc] + scr[cc + 128];
        g_psq[p]  = scr[256 + cc] + scr[256 + cc + 128];
    }
}

// ---------------- kernel 3: reduce partials, fold BN into scale/shift ------
__global__ void __launch_bounds__(256) stats_kernel(const float* __restrict__ gamma,
                                                    const float* __restrict__ beta) {
    const int c = blockIdx.x;
    const int tid = threadIdx.x;
    __shared__ float s1[256], s2[256];
    float a = 0.f, b2 = 0.f;
    for (int i = tid; i < NBLK2; i += 256) {
        a += g_psum[i * CC + c];
        b2 += g_psq[i * CC + c];
    }
    s1[tid] = a; s2[tid] = b2;
    __syncthreads();
    for (int s = 128; s > 0; s >>= 1) {
        if (tid < s) { s1[tid] += s1[tid + s]; s2[tid] += s2[tid + s]; }
        __syncthreads();
    }
    if (tid == 0) {
        const float inv = 1.f / (float)(NB * TT * VV);
        float mean = s1[0] * inv;
        float var = s2[0] * inv - mean * mean;
        float sc = gamma[c] * rsqrtf(var + BN_EPS);
        g_scale[c] = sc;
        g_shift[c] = beta[c] - mean * sc;
    }
}

// ---------------- kernel 4: in-place normalize + A passthrough tail --------
__global__ void normalize_kernel(float* __restrict__ out,
                                 const float* __restrict__ A,
                                 int out_size) {
    const int total4 = NELEM / 4;
    int stride = gridDim.x * blockDim.x;
    for (int idx = blockIdx.x * blockDim.x + threadIdx.x; idx < total4; idx += stride) {
        int e = idx * 4;
        int c = (e / TV) % CC;
        float sc = g_scale[c], sh = g_shift[c];
        float4 v = ((float4*)out)[idx];
        v.x = fmaf(v.x, sc, sh);
        v.y = fmaf(v.y, sc, sh);
        v.z = fmaf(v.z, sc, sh);
        v.w = fmaf(v.w, sc, sh);
        ((float4*)out)[idx] = v;
    }
    if (out_size > NELEM) {
        for (int j = blockIdx.x * blockDim.x + threadIdx.x;
             j < out_size - NELEM && j < KK * VV * VV; j += stride)
            out[NELEM + j] = A[j];
    }
}

// ---------------- launch ----------------------------------------------------
extern "C" void kernel_launch(void* const* d_in, const int* in_sizes, int n_in,
                              void* d_out, int out_size) {
    const float* x     = (const float*)d_in[0];
    const float* A     = (const float*)d_in[1];
    const float* W     = (const float*)d_in[2];
    const float* b     = (const float*)d_in[3];
    const float* gamma = (const float*)d_in[4];
    const float* beta  = (const float*)d_in[5];
    float* out = (float*)d_out;

    cudaFuncSetAttribute(mgemm_kernel,
                         cudaFuncAttributeMaxDynamicSharedMemorySize, SMEM_M_TOTAL);

    dummy_kernel<<<1, 32>>>();                 // keeps ncu slot 3 on mgemm

    prep_kernel<<<64, 256>>>(W, b, A);

    dim3 gz(TT / 10, NB);                      // (30, 64)
    zgemm_kernel<<<gz, 256>>>(x, A);

    dim3 gm(MBLK, NB);                         // (59, 64)
    mgemm_kernel<<<gm, 256, SMEM_M_TOTAL>>>(x, out);

    stats_kernel<<<CC, 256>>>(gamma, beta);

    normalize_kernel<<<2048, 256>>>(out, A, out_size);
}

// round 16
// speedup vs baseline: 1.4782x; 1.4782x over previous
#include <cuda_runtime.h>
#include <cuda_fp16.h>
#include <cstdint>

// Problem constants
#define NB   64            // batch
#define CC   128           // channels
#define TT   300           // time
#define VV   25            // vertices
#define KK   3             // adjacency count
#define TV   (TT*VV)       // 7500 rows per n (r = t*25+w)
#define KD   (KK*CC)       // 384 = main GEMM K-dim
#define NELEM (NB*CC*TT*VV) // 61,440,000 output elems
#define BN_EPS 1e-5f
#define RPAD 7552          // padded rows per n for g_z (59*128)
#define XS 40              // zgemm sX row stride (fp16)
#define SS 136             // zgemm stage row stride (fp16)
#define MBLK 59            // mgemm row-blocks per n
#define NBLK2 (MBLK*NB)    // 3776 stats partials
#define KH 64              // mgemm chunk K size
#define KPH 72             // mgemm smem row stride (halfs)

typedef unsigned long long u64;

// ---------------- fp16 mma.sync + cp.async (base PTX, plain sm_103) ---------
__device__ __forceinline__ void mma16816(float* c, const uint32_t* a, const uint32_t* b) {
    asm volatile(
        "mma.sync.aligned.m16n8k16.row.col.f32.f16.f16.f32 "
        "{%0,%1,%2,%3}, {%4,%5,%6,%7}, {%8,%9}, {%0,%1,%2,%3};"
        : "+f"(c[0]), "+f"(c[1]), "+f"(c[2]), "+f"(c[3])
        : "r"(a[0]), "r"(a[1]), "r"(a[2]), "r"(a[3]), "r"(b[0]), "r"(b[1]));
}
__device__ __forceinline__ uint32_t smem_u32(const void* p) {
    uint32_t a;
    asm("{ .reg .u64 t; cvta.to.shared.u64 t, %1; cvt.u32.u64 %0, t; }"
        : "=r"(a) : "l"(p));
    return a;
}
__device__ __forceinline__ void cpa16(uint32_t s, const void* g) {
    asm volatile("cp.async.cg.shared.global [%0], [%1], 16;" :: "r"(s), "l"(g));
}
#define CP_COMMIT() asm volatile("cp.async.commit_group;" ::: "memory")
#define CP_WAIT(N)  asm volatile("cp.async.wait_group %0;" :: "n"(N) : "memory")

// ---------------- scratch ----------------------------------------------------
__device__ __half g_z[(size_t)NB * RPAD * KD];   // z[n][r][(k,ci)] fp16
__device__ __half g_W2[CC * KD];                 // W2[c][(k,ci)] fp16
__device__ float g_bias2[CC * VV];               // bias folded through A
__device__ float g_psum[NBLK2 * CC];
__device__ float g_psq[NBLK2 * CC];
__device__ float g_scale[CC];
__device__ float g_shift[CC];

// ---------------- kernel -1: dummy (keeps ncu's profiled slot on mgemm) -----
__global__ void dummy_kernel() {}

// ---------------- kernel 0: prep (W2 fp16 permuted, fold bias) --------------
__global__ void prep_kernel(const float* __restrict__ W,
                            const float* __restrict__ b,
                            const float* __restrict__ A) {
    int tid = blockIdx.x * blockDim.x + threadIdx.x;
    int stride = gridDim.x * blockDim.x;
    for (int i = tid; i < CC * KD; i += stride) {
        int c = i / KD, rem = i - c * KD;
        int k = rem >> 7, ci = rem & 127;
        g_W2[i] = __float2half(W[(k * CC + c) * CC + ci]);
    }
    for (int i = tid; i < CC * VV; i += stride) {
        int c = i / VV, w = i % VV;
        float s = 0.f;
        #pragma unroll
        for (int k = 0; k < KK; k++) {
            float cs = 0.f;
            #pragma unroll
            for (int v = 0; v < VV; v++) cs += A[k * VV * VV + v * VV + w];
            s += b[k * CC + c] * cs;
        }
        g_bias2[i] = s;
    }
}

// ---------------- kernel 1: z-GEMM (unchanged from R14) ----------------------
__global__ void __launch_bounds__(256) zgemm_kernel(const float* __restrict__ x,
                                                    const float* __restrict__ A) {
    __shared__ __half sX[128 * XS];       // [ci][v] padded
    __shared__ __half sBA[96 * XS];       // [(k*25+w)][v] padded, A transposed
    __shared__ __half stage[96 * SS];     // [(k,w)][ci]

    const int tb = blockIdx.x, n = blockIdx.y;
    const int tid = threadIdx.x;
    const int wid = tid >> 5, lane = tid & 31;
    const int wm = wid & 3, wn = wid >> 2;
    const int lr = lane >> 2, kq = (lane & 3) * 2;
    const float* xn0 = x + (size_t)(n * CC) * TV;

    for (int e = tid; e < 128 * XS; e += 256) sX[e] = __float2half(0.f);
    for (int e = tid; e < 96 * XS; e += 256) sBA[e] = __float2half(0.f);
    __syncthreads();
    for (int e = tid; e < KK * VV * VV; e += 256) {
        int k = e / (VV * VV), rem = e - k * VV * VV;
        int v = rem / VV, w = rem - v * VV;
        sBA[(k * VV + w) * XS + v] = __float2half(A[e]);
    }
    {
        const float* xn = xn0 + (tb * 10) * VV;
        for (int e = tid; e < CC * VV; e += 256)
            sX[(e / VV) * XS + e % VV] = __float2half(xn[(size_t)(e / VV) * TV + e % VV]);
    }
    __syncthreads();

    for (int tt = 0; tt < 10; tt++) {
        const int t = tb * 10 + tt;

        float acc[2][6][4];
        #pragma unroll
        for (int mt = 0; mt < 2; mt++)
            #pragma unroll
            for (int nt = 0; nt < 6; nt++)
                #pragma unroll
                for (int j = 0; j < 4; j++) acc[mt][nt][j] = 0.f;

        #pragma unroll
        for (int kk = 0; kk < 2; kk++) {
            const int k0 = kk * 16 + kq;
            uint32_t af[2][4], bf[6][2];
            #pragma unroll
            for (int mt = 0; mt < 2; mt++) {
                int rm = wm * 32 + mt * 16 + lr;
                af[mt][0] = *(const uint32_t*)(sX + rm * XS + k0);
                af[mt][1] = *(const uint32_t*)(sX + (rm + 8) * XS + k0);
                af[mt][2] = *(const uint32_t*)(sX + rm * XS + k0 + 8);
                af[mt][3] = *(const uint32_t*)(sX + (rm + 8) * XS + k0 + 8);
            }
            #pragma unroll
            for (int nt = 0; nt < 6; nt++) {
                int rn = wn * 48 + nt * 8 + lr;
                bf[nt][0] = *(const uint32_t*)(sBA + rn * XS + k0);
                bf[nt][1] = *(const uint32_t*)(sBA + rn * XS + k0 + 8);
            }
            #pragma unroll
            for (int mt = 0; mt < 2; mt++)
                #pragma unroll
                for (int nt = 0; nt < 6; nt++)
                    mma16816(acc[mt][nt], af[mt], bf[nt]);
        }

        #pragma unroll
        for (int mt = 0; mt < 2; mt++) {
            int row = wm * 32 + mt * 16 + lr;
            #pragma unroll
            for (int nt = 0; nt < 6; nt++) {
                int col = wn * 48 + nt * 8 + kq;
                stage[col * SS + row]           = __float2half(acc[mt][nt][0]);
                stage[(col + 1) * SS + row]     = __float2half(acc[mt][nt][1]);
                stage[col * SS + row + 8]       = __float2half(acc[mt][nt][2]);
                stage[(col + 1) * SS + row + 8] = __float2half(acc[mt][nt][3]);
            }
        }
        __syncthreads();

        __half* zb = g_z + ((size_t)n * RPAD + t * VV) * KD;
        for (int e = tid; e < 75 * 16; e += 256) {
            int q = e >> 4, h8 = (e & 15);
            int k = q / VV, w = q - k * VV;
            *(uint4*)(zb + (size_t)w * KD + k * CC + h8 * 8) =
                *(const uint4*)(stage + q * SS + h8 * 8);
        }
        if (tt < 9) {
            const float* xn = xn0 + (t + 1) * VV;
            for (int e = tid; e < CC * VV; e += 256)
                sX[(e / VV) * XS + e % VV] = __float2half(xn[(size_t)(e / VV) * TV + e % VV]);
        }
        __syncthreads();
    }
}

// ---------------- kernel 2: main GEMM, sA-only 2-stage pipeline -------------
// sA (DRAM z stream) double-buffered; sB (L2-hot W2) single-buffered.
// Commit order sB(ch) then sA(ch+1): wait_group 1 completes sA(ch)+sB(ch)
// while sA(ch+1) flies through the mma phase. Forced 2 CTA/SM via
// __launch_bounds__(256, 2) (regs capped at 128).
#define SMEM_SA0 0
#define SMEM_SA1 18432
#define SMEM_SB  36864
#define SMEM_SCR 66560            // out_s epilogue alias needs 0..66560
#define SMEM_M_TOTAL (66560 + 2048)

__global__ void __launch_bounds__(256, 2) mgemm_kernel(const float* __restrict__ x,
                                                       float* __restrict__ out) {
    extern __shared__ char sm[];
    float* out_s = (float*)sm;                  // [128 c][130] epilogue alias
    float* scr = (float*)(sm + SMEM_SCR);       // 512 floats

    const int r0 = blockIdx.x * 128;
    const int n  = blockIdx.y;
    const int tid = threadIdx.x;
    const int wid = tid >> 5, lane = tid & 31;
    const int wm = wid & 1, wn = wid >> 1;
    const int lr = lane >> 2, kq = (lane & 3) * 2;
    const int crow = tid >> 3, cc8 = (tid & 7) * 8;   // copy coords: 1024 chunks

    const __half* srcA0 = g_z + ((size_t)n * RPAD + r0) * KD + (size_t)crow * KD + cc8;
    const __half* srcB0 = g_W2 + (size_t)crow * KD + cc8;
    const uint32_t smbase = smem_u32(sm);
    const uint32_t dOff = (crow * KPH + cc8) * 2;

    // prologue: sA chunk 0 -> buf0
    #pragma unroll
    for (int i = 0; i < 4; i++)
        cpa16(smbase + SMEM_SA0 + dOff + i * 32 * KPH * 2, srcA0 + (size_t)i * 32 * KD);
    CP_COMMIT();

    float acc[4][4][4];
    #pragma unroll
    for (int mt = 0; mt < 4; mt++)
        #pragma unroll
        for (int nt = 0; nt < 4; nt++)
            #pragma unroll
            for (int j = 0; j < 4; j++) acc[mt][nt][j] = 0.f;

    #pragma unroll
    for (int ch = 0; ch < 6; ch++) {
        // sB(ch) -- L2-hot
        #pragma unroll
        for (int i = 0; i < 4; i++)
            cpa16(smbase + SMEM_SB + dOff + i * 32 * KPH * 2,
                  srcB0 + ch * KH + (size_t)i * 32 * KD);
        CP_COMMIT();
        // sA(ch+1) -> other buffer
        if (ch < 5) {
            uint32_t dA = ((ch + 1) & 1) ? SMEM_SA1 : SMEM_SA0;
            #pragma unroll
            for (int i = 0; i < 4; i++)
                cpa16(smbase + dA + dOff + i * 32 * KPH * 2,
                      srcA0 + (ch + 1) * KH + (size_t)i * 32 * KD);
            CP_COMMIT();
            CP_WAIT(1);            // sA(ch), sB(ch) done; sA(ch+1) in flight
        } else {
            CP_WAIT(0);
        }
        __syncthreads();

        const __half* sA = (const __half*)(sm + ((ch & 1) ? SMEM_SA1 : SMEM_SA0));
        const __half* sB = (const __half*)(sm + SMEM_SB);
        #pragma unroll
        for (int kk = 0; kk < 4; kk++) {
            const int k0 = kk * 16 + kq;
            uint32_t af[4][4], bf[4][2];
            #pragma unroll
            for (int mt = 0; mt < 4; mt++) {
                int rm = wm * 64 + mt * 16 + lr;
                af[mt][0] = *(const uint32_t*)(sA + rm * KPH + k0);
                af[mt][1] = *(const uint32_t*)(sA + (rm + 8) * KPH + k0);
                af[mt][2] = *(const uint32_t*)(sA + rm * KPH + k0 + 8);
                af[mt][3] = *(const uint32_t*)(sA + (rm + 8) * KPH + k0 + 8);
            }
            #pragma unroll
            for (int nt = 0; nt < 4; nt++) {
                int rn = wn * 32 + nt * 8 + lr;
                bf[nt][0] = *(const uint32_t*)(sB + rn * KPH + k0);
                bf[nt][1] = *(const uint32_t*)(sB + rn * KPH + k0 + 8);
            }
            #pragma unroll
            for (int mt = 0; mt < 4; mt++)
                #pragma unroll
                for (int nt = 0; nt < 4; nt++)
                    mma16816(acc[mt][nt], af[mt], bf[nt]);
        }
        __syncthreads();   // all warps done with sB / sA(ch) before refill
    }

    // stage D: out_s[c][r_loc]  (aliases pipeline buffers)
    #pragma unroll
    for (int mt = 0; mt < 4; mt++) {
        int r_loc = wm * 64 + mt * 16 + lr;
        #pragma unroll
        for (int nt = 0; nt < 4; nt++) {
            int cb = wn * 32 + nt * 8 + kq;
            out_s[cb * 130 + r_loc]           = acc[mt][nt][0];
            out_s[(cb + 1) * 130 + r_loc]     = acc[mt][nt][1];
            out_s[cb * 130 + r_loc + 8]       = acc[mt][nt][2];
            out_s[(cb + 1) * 130 + r_loc + 8] = acc[mt][nt][3];
        }
    }
    __syncthreads();

    // Phase A: bias + residual + relu; write out; keep in smem for stats
    for (int e = tid; e < 128 * 128; e += 256) {
        int c = e >> 7, r = e & 127;
        int gr = r0 + r;
        if (gr < TV) {
            size_t gidx = (size_t)(n * CC + c) * TV + gr;
            float v = out_s[c * 130 + r] + g_bias2[c * VV + gr % VV] + x[gidx];
            v = fmaxf(v, 0.f);
            out_s[c * 130 + r] = v;
            out[gidx] = v;
        }
    }
    __syncthreads();

    // Phase B: per-channel stats partials
    const int cc = tid & 127, th = tid >> 7;
    const int rmax = (TV - r0 < 128) ? (TV - r0) : 128;
    float bs = 0.f, bq = 0.f;
    for (int r = th; r < rmax; r += 2) {
        float v = out_s[cc * 130 + r];
        bs += v; bq += v * v;
    }
    scr[tid] = bs; scr[256 + tid] = bq;
    __syncthreads();
    if (th == 0) {
        int p = (n * MBLK + blockIdx.x) * CC + cc;
        g_psum[p] = scr[cc] + scr[cc + 128];
        g_psq[p]  = scr[256 + cc] + scr[256 + cc + 128];
    }
}

// ---------------- kernel 3: reduce partials, fold BN into scale/shift ------
__global__ void __launch_bounds__(256) stats_kernel(const float* __restrict__ gamma,
                                                    const float* __restrict__ beta) {
    const int c = blockIdx.x;
    const int tid = threadIdx.x;
    __shared__ float s1[256], s2[256];
    float a = 0.f, b2 = 0.f;
    for (int i = tid; i < NBLK2; i += 256) {
        a += g_psum[i * CC + c];
        b2 += g_psq[i * CC + c];
    }
    s1[tid] = a; s2[tid] = b2;
    __syncthreads();
    for (int s = 128; s > 0; s >>= 1) {
        if (tid < s) { s1[tid] += s1[tid + s]; s2[tid] += s2[tid + s]; }
        __syncthreads();
    }
    if (tid == 0) {
        const float inv = 1.f / (float)(NB * TT * VV);
        float mean = s1[0] * inv;
        float var = s2[0] * inv - mean * mean;
        float sc = gamma[c] * rsqrtf(var + BN_EPS);
        g_scale[c] = sc;
        g_shift[c] = beta[c] - mean * sc;
    }
}

// ---------------- kernel 4: in-place normalize + A passthrough tail --------
__global__ void normalize_kernel(float* __restrict__ out,
                                 const float* __restrict__ A,
                                 int out_size) {
    const int total4 = NELEM / 4;
    int stride = gridDim.x * blockDim.x;
    for (int idx = blockIdx.x * blockDim.x + threadIdx.x; idx < total4; idx += stride) {
        int e = idx * 4;
        int c = (e / TV) % CC;
        float sc = g_scale[c], sh = g_shift[c];
        float4 v = ((float4*)out)[idx];
        v.x = fmaf(v.x, sc, sh);
        v.y = fmaf(v.y, sc, sh);
        v.z = fmaf(v.z, sc, sh);
        v.w = fmaf(v.w, sc, sh);
        ((float4*)out)[idx] = v;
    }
    if (out_size > NELEM) {
        for (int j = blockIdx.x * blockDim.x + threadIdx.x;
             j < out_size - NELEM && j < KK * VV * VV; j += stride)
            out[NELEM + j] = A[j];
    }
}

// ---------------- launch ----------------------------------------------------
extern "C" void kernel_launch(void* const* d_in, const int* in_sizes, int n_in,
                              void* d_out, int out_size) {
    const float* x     = (const float*)d_in[0];
    const float* A     = (const float*)d_in[1];
    const float* W     = (const float*)d_in[2];
    const float* b     = (const float*)d_in[3];
    const float* gamma = (const float*)d_in[4];
    const float* beta  = (const float*)d_in[5];
    float* out = (float*)d_out;

    cudaFuncSetAttribute(mgemm_kernel,
                         cudaFuncAttributeMaxDynamicSharedMemorySize, SMEM_M_TOTAL);

    dummy_kernel<<<1, 32>>>();                 // keeps ncu slot 3 on mgemm

    prep_kernel<<<64, 256>>>(W, b, A);

    dim3 gz(TT / 10, NB);                      // (30, 64)
    zgemm_kernel<<<gz, 256>>>(x, A);

    dim3 gm(MBLK, NB);                         // (59, 64)
    mgemm_kernel<<<gm, 256, SMEM_M_TOTAL>>>(x, out);

    stats_kernel<<<CC, 256>>>(gamma, beta);

    normalize_kernel<<<2048, 256>>>(out, A, out_size);
}

// round 17
// speedup vs baseline: 1.7638x; 1.1932x over previous
#include <cuda_runtime.h>
#include <cuda_fp16.h>
#include <cstdint>

// Problem constants
#define NB   64            // batch
#define CC   128           // channels
#define TT   300           // time
#define VV   25            // vertices
#define KK   3             // adjacency count
#define TV   (TT*VV)       // 7500 rows per n (r = t*25+w)
#define KD   (KK*CC)       // 384 = main GEMM K-dim
#define NELEM (NB*CC*TT*VV) // 61,440,000 output elems
#define BN_EPS 1e-5f
#define RPAD 7552          // padded rows per n for g_z (59*128)
#define XS 40              // zgemm sX row stride (fp16)
#define SS 136             // zgemm stage row stride (fp16)
#define MBLK 59            // mgemm row-blocks per n
#define NBLK2 (MBLK*NB)    // 3776 stats partials
#define KH 64              // mgemm chunk K size
#define KPH 72             // mgemm smem row stride (halfs)

typedef unsigned long long u64;

// ---------------- fp16 mma.sync + cp.async (base PTX, plain sm_103) ---------
__device__ __forceinline__ void mma16816(float* c, const uint32_t* a, const uint32_t* b) {
    asm volatile(
        "mma.sync.aligned.m16n8k16.row.col.f32.f16.f16.f32 "
        "{%0,%1,%2,%3}, {%4,%5,%6,%7}, {%8,%9}, {%0,%1,%2,%3};"
        : "+f"(c[0]), "+f"(c[1]), "+f"(c[2]), "+f"(c[3])
        : "r"(a[0]), "r"(a[1]), "r"(a[2]), "r"(a[3]), "r"(b[0]), "r"(b[1]));
}
__device__ __forceinline__ uint32_t smem_u32(const void* p) {
    uint32_t a;
    asm("{ .reg .u64 t; cvta.to.shared.u64 t, %1; cvt.u32.u64 %0, t; }"
        : "=r"(a) : "l"(p));
    return a;
}
__device__ __forceinline__ void cpa16(uint32_t s, const void* g) {
    asm volatile("cp.async.cg.shared.global [%0], [%1], 16;" :: "r"(s), "l"(g));
}
#define CP_COMMIT() asm volatile("cp.async.commit_group;" ::: "memory")
#define CP_WAIT(N)  asm volatile("cp.async.wait_group %0;" :: "n"(N) : "memory")

// ---------------- scratch ----------------------------------------------------
__device__ __half g_z[(size_t)NB * RPAD * KD];   // z[n][r][(k,ci)] fp16
__device__ __half g_W2[CC * KD];                 // W2[c][(k,ci)] fp16
__device__ float g_bias2[CC * VV];               // bias folded through A
__device__ float g_psum[NBLK2 * CC];
__device__ float g_psq[NBLK2 * CC];
__device__ float g_scale[CC];
__device__ float g_shift[CC];

// ---------------- kernel -1: dummy (keeps ncu's profiled slot on mgemm) -----
__global__ void dummy_kernel() {}

// ---------------- kernel 0: prep (W2 fp16 permuted, fold bias) --------------
__global__ void prep_kernel(const float* __restrict__ W,
                            const float* __restrict__ b,
                            const float* __restrict__ A) {
    int tid = blockIdx.x * blockDim.x + threadIdx.x;
    int stride = gridDim.x * blockDim.x;
    for (int i = tid; i < CC * KD; i += stride) {
        int c = i / KD, rem = i - c * KD;
        int k = rem >> 7, ci = rem & 127;
        g_W2[i] = __float2half(W[(k * CC + c) * CC + ci]);
    }
    for (int i = tid; i < CC * VV; i += stride) {
        int c = i / VV, w = i % VV;
        float s = 0.f;
        #pragma unroll
        for (int k = 0; k < KK; k++) {
            float cs = 0.f;
            #pragma unroll
            for (int v = 0; v < VV; v++) cs += A[k * VV * VV + v * VV + w];
            s += b[k * CC + c] * cs;
        }
        g_bias2[i] = s;
    }
}

// ---------------- kernel 1: z-GEMM (unchanged from R14/R16) ------------------
__global__ void __launch_bounds__(256) zgemm_kernel(const float* __restrict__ x,
                                                    const float* __restrict__ A) {
    __shared__ __half sX[128 * XS];       // [ci][v] padded
    __shared__ __half sBA[96 * XS];       // [(k*25+w)][v] padded, A transposed
    __shared__ __half stage[96 * SS];     // [(k,w)][ci]

    const int tb = blockIdx.x, n = blockIdx.y;
    const int tid = threadIdx.x;
    const int wid = tid >> 5, lane = tid & 31;
    const int wm = wid & 3, wn = wid >> 2;
    const int lr = lane >> 2, kq = (lane & 3) * 2;
    const float* xn0 = x + (size_t)(n * CC) * TV;

    for (int e = tid; e < 128 * XS; e += 256) sX[e] = __float2half(0.f);
    for (int e = tid; e < 96 * XS; e += 256) sBA[e] = __float2half(0.f);
    __syncthreads();
    for (int e = tid; e < KK * VV * VV; e += 256) {
        int k = e / (VV * VV), rem = e - k * VV * VV;
        int v = rem / VV, w = rem - v * VV;
        sBA[(k * VV + w) * XS + v] = __float2half(A[e]);
    }
    {
        const float* xn = xn0 + (tb * 10) * VV;
        for (int e = tid; e < CC * VV; e += 256)
            sX[(e / VV) * XS + e % VV] = __float2half(xn[(size_t)(e / VV) * TV + e % VV]);
    }
    __syncthreads();

    for (int tt = 0; tt < 10; tt++) {
        const int t = tb * 10 + tt;

        float acc[2][6][4];
        #pragma unroll
        for (int mt = 0; mt < 2; mt++)
            #pragma unroll
            for (int nt = 0; nt < 6; nt++)
                #pragma unroll
                for (int j = 0; j < 4; j++) acc[mt][nt][j] = 0.f;

        #pragma unroll
        for (int kk = 0; kk < 2; kk++) {
            const int k0 = kk * 16 + kq;
            uint32_t af[2][4], bf[6][2];
            #pragma unroll
            for (int mt = 0; mt < 2; mt++) {
                int rm = wm * 32 + mt * 16 + lr;
                af[mt][0] = *(const uint32_t*)(sX + rm * XS + k0);
                af[mt][1] = *(const uint32_t*)(sX + (rm + 8) * XS + k0);
                af[mt][2] = *(const uint32_t*)(sX + rm * XS + k0 + 8);
                af[mt][3] = *(const uint32_t*)(sX + (rm + 8) * XS + k0 + 8);
            }
            #pragma unroll
            for (int nt = 0; nt < 6; nt++) {
                int rn = wn * 48 + nt * 8 + lr;
                bf[nt][0] = *(const uint32_t*)(sBA + rn * XS + k0);
                bf[nt][1] = *(const uint32_t*)(sBA + rn * XS + k0 + 8);
            }
            #pragma unroll
            for (int mt = 0; mt < 2; mt++)
                #pragma unroll
                for (int nt = 0; nt < 6; nt++)
                    mma16816(acc[mt][nt], af[mt], bf[nt]);
        }

        #pragma unroll
        for (int mt = 0; mt < 2; mt++) {
            int row = wm * 32 + mt * 16 + lr;
            #pragma unroll
            for (int nt = 0; nt < 6; nt++) {
                int col = wn * 48 + nt * 8 + kq;
                stage[col * SS + row]           = __float2half(acc[mt][nt][0]);
                stage[(col + 1) * SS + row]     = __float2half(acc[mt][nt][1]);
                stage[col * SS + row + 8]       = __float2half(acc[mt][nt][2]);
                stage[(col + 1) * SS + row + 8] = __float2half(acc[mt][nt][3]);
            }
        }
        __syncthreads();

        __half* zb = g_z + ((size_t)n * RPAD + t * VV) * KD;
        for (int e = tid; e < 75 * 16; e += 256) {
            int q = e >> 4, h8 = (e & 15);
            int k = q / VV, w = q - k * VV;
            *(uint4*)(zb + (size_t)w * KD + k * CC + h8 * 8) =
                *(const uint4*)(stage + q * SS + h8 * 8);
        }
        if (tt < 9) {
            const float* xn = xn0 + (t + 1) * VV;
            for (int e = tid; e < CC * VV; e += 256)
                sX[(e / VV) * XS + e % VV] = __float2half(xn[(size_t)(e / VV) * TV + e % VV]);
        }
        __syncthreads();
    }
}

// ---------------- kernel 2: main GEMM, 128x64 tile, 3 CTA/SM ----------------
// Each CTA: 128 rows x 64 channels (half = blockIdx.x & 1, lowest bit so the
// two halves of one z-tile are adjacent -> z re-read hits L2). sA (z stream)
// double-buffered cp.async; sB single. __launch_bounds__(256,3) caps regs.
#define SMEM_SA0 0
#define SMEM_SA1 18432
#define SMEM_SB  36864            // 64 rows x KPH halfs = 9216 B
#define SMEM_SCR 46080
#define SMEM_M_TOTAL (46080 + 2048)

__global__ void __launch_bounds__(256, 3) mgemm_kernel(const float* __restrict__ x,
                                                       float* __restrict__ out) {
    extern __shared__ char sm[];
    float* out_s = (float*)sm;                  // [64 c][130] epilogue alias
    float* scr = (float*)(sm + SMEM_SCR);       // 512 floats

    const int half = blockIdx.x & 1;
    const int bx = blockIdx.x >> 1;
    const int r0 = bx * 128;
    const int n  = blockIdx.y;
    const int tid = threadIdx.x;
    const int wid = tid >> 5, lane = tid & 31;
    const int wm = wid & 3, wn = wid >> 2;       // wm: 32-row group, wn: 32-col group
    const int lr = lane >> 2, kq = (lane & 3) * 2;
    const int crow = tid >> 3, cc8 = (tid & 7) * 8;   // copy coords

    const __half* srcA0 = g_z + ((size_t)n * RPAD + r0) * KD + (size_t)crow * KD + cc8;
    const __half* srcB0 = g_W2 + (size_t)(half * 64 + crow) * KD + cc8;
    const uint32_t smbase = smem_u32(sm);
    const uint32_t dOff = (crow * KPH + cc8) * 2;

    // prologue: sA chunk 0 -> buf0 (128 rows x 64 halfs)
    #pragma unroll
    for (int i = 0; i < 4; i++)
        cpa16(smbase + SMEM_SA0 + dOff + i * 32 * KPH * 2, srcA0 + (size_t)i * 32 * KD);
    CP_COMMIT();

    float acc[2][4][4];
    #pragma unroll
    for (int mt = 0; mt < 2; mt++)
        #pragma unroll
        for (int nt = 0; nt < 4; nt++)
            #pragma unroll
            for (int j = 0; j < 4; j++) acc[mt][nt][j] = 0.f;

    #pragma unroll
    for (int ch = 0; ch < 6; ch++) {
        // sB(ch): 64 rows x 64 halfs (L2-hot W2)
        #pragma unroll
        for (int i = 0; i < 2; i++)
            cpa16(smbase + SMEM_SB + dOff + i * 32 * KPH * 2,
                  srcB0 + ch * KH + (size_t)i * 32 * KD);
        CP_COMMIT();
        // sA(ch+1) -> other buffer
        if (ch < 5) {
            uint32_t dA = ((ch + 1) & 1) ? SMEM_SA1 : SMEM_SA0;
            #pragma unroll
            for (int i = 0; i < 4; i++)
                cpa16(smbase + dA + dOff + i * 32 * KPH * 2,
                      srcA0 + (ch + 1) * KH + (size_t)i * 32 * KD);
            CP_COMMIT();
            CP_WAIT(1);            // sA(ch), sB(ch) done; sA(ch+1) in flight
        } else {
            CP_WAIT(0);
        }
        __syncthreads();

        const __half* sA = (const __half*)(sm + ((ch & 1) ? SMEM_SA1 : SMEM_SA0));
        const __half* sB = (const __half*)(sm + SMEM_SB);
        #pragma unroll
        for (int kk = 0; kk < 4; kk++) {
            const int k0 = kk * 16 + kq;
            uint32_t af[2][4], bf[4][2];
            #pragma unroll
            for (int mt = 0; mt < 2; mt++) {
                int rm = wm * 32 + mt * 16 + lr;
                af[mt][0] = *(const uint32_t*)(sA + rm * KPH + k0);
                af[mt][1] = *(const uint32_t*)(sA + (rm + 8) * KPH + k0);
                af[mt][2] = *(const uint32_t*)(sA + rm * KPH + k0 + 8);
                af[mt][3] = *(const uint32_t*)(sA + (rm + 8) * KPH + k0 + 8);
            }
            #pragma unroll
            for (int nt = 0; nt < 4; nt++) {
                int rn = wn * 32 + nt * 8 + lr;
                bf[nt][0] = *(const uint32_t*)(sB + rn * KPH + k0);
                bf[nt][1] = *(const uint32_t*)(sB + rn * KPH + k0 + 8);
            }
            #pragma unroll
            for (int mt = 0; mt < 2; mt++)
                #pragma unroll
                for (int nt = 0; nt < 4; nt++)
                    mma16816(acc[mt][nt], af[mt], bf[nt]);
        }
        __syncthreads();   // all warps done with sB / sA(ch) before refill
    }

    // stage D: out_s[c_loc][r_loc]  (aliases pipeline buffers)
    #pragma unroll
    for (int mt = 0; mt < 2; mt++) {
        int r_loc = wm * 32 + mt * 16 + lr;
        #pragma unroll
        for (int nt = 0; nt < 4; nt++) {
            int cb = wn * 32 + nt * 8 + kq;
            out_s[cb * 130 + r_loc]           = acc[mt][nt][0];
            out_s[(cb + 1) * 130 + r_loc]     = acc[mt][nt][1];
            out_s[cb * 130 + r_loc + 8]       = acc[mt][nt][2];
            out_s[(cb + 1) * 130 + r_loc + 8] = acc[mt][nt][3];
        }
    }
    __syncthreads();

    // Phase A: bias + residual + relu; write out; keep in smem for stats
    for (int e = tid; e < 64 * 128; e += 256) {
        int c = e >> 7, r = e & 127;
        int gr = r0 + r;
        if (gr < TV) {
            int gc = half * 64 + c;
            size_t gidx = (size_t)(n * CC + gc) * TV + gr;
            float v = out_s[c * 130 + r] + g_bias2[gc * VV + gr % VV] + x[gidx];
            v = fmaxf(v, 0.f);
            out_s[c * 130 + r] = v;
            out[gidx] = v;
        }
    }
    __syncthreads();

    // Phase B: per-channel stats partials (4 threads per channel)
    const int cc = tid & 63, th = tid >> 6;
    const int rmax = (TV - r0 < 128) ? (TV - r0) : 128;
    float bs = 0.f, bq = 0.f;
    for (int r = th; r < rmax; r += 4) {
        float v = out_s[cc * 130 + r];
        bs += v; bq += v * v;
    }
    scr[tid] = bs; scr[256 + tid] = bq;
    __syncthreads();
    if (th == 0) {
        int p = (n * MBLK + bx) * CC + half * 64 + cc;
        g_psum[p] = scr[cc] + scr[cc + 64] + scr[cc + 128] + scr[cc + 192];
        g_psq[p]  = scr[256 + cc] + scr[256 + cc + 64]
                  + scr[256 + cc + 128] + scr[256 + cc + 192];
    }
}

// ---------------- kernel 3: reduce partials, fold BN into scale/shift ------
__global__ void __launch_bounds__(256) stats_kernel(const float* __restrict__ gamma,
                                                    const float* __restrict__ beta) {
    const int c = blockIdx.x;
    const int tid = threadIdx.x;
    __shared__ float s1[256], s2[256];
    float a = 0.f, b2 = 0.f;
    for (int i = tid; i < NBLK2; i += 256) {
        a += g_psum[i * CC + c];
        b2 += g_psq[i * CC + c];
    }
    s1[tid] = a; s2[tid] = b2;
    __syncthreads();
    for (int s = 128; s > 0; s >>= 1) {
        if (tid < s) { s1[tid] += s1[tid + s]; s2[tid] += s2[tid + s]; }
        __syncthreads();
    }
    if (tid == 0) {
        const float inv = 1.f / (float)(NB * TT * VV);
        float mean = s1[0] * inv;
        float var = s2[0] * inv - mean * mean;
        float sc = gamma[c] * rsqrtf(var + BN_EPS);
        g_scale[c] = sc;
        g_shift[c] = beta[c] - mean * sc;
    }
}

// ---------------- kernel 4: in-place normalize + A passthrough tail --------
__global__ void normalize_kernel(float* __restrict__ out,
                                 const float* __restrict__ A,
                                 int out_size) {
    const int total4 = NELEM / 4;
    int stride = gridDim.x * blockDim.x;
    for (int idx = blockIdx.x * blockDim.x + threadIdx.x; idx < total4; idx += stride) {
        int e = idx * 4;
        int c = (e / TV) % CC;
        float sc = g_scale[c], sh = g_shift[c];
        float4 v = ((float4*)out)[idx];
        v.x = fmaf(v.x, sc, sh);
        v.y = fmaf(v.y, sc, sh);
        v.z = fmaf(v.z, sc, sh);
        v.w = fmaf(v.w, sc, sh);
        ((float4*)out)[idx] = v;
    }
    if (out_size > NELEM) {
        for (int j = blockIdx.x * blockDim.x + threadIdx.x;
             j < out_size - NELEM && j < KK * VV * VV; j += stride)
            out[NELEM + j] = A[j];
    }
}

// ---------------- launch ----------------------------------------------------
extern "C" void kernel_launch(void* const* d_in, const int* in_sizes, int n_in,
                              void* d_out, int out_size) {
    const float* x     = (const float*)d_in[0];
    const float* A     = (const float*)d_in[1];
    const float* W     = (const float*)d_in[2];
    const float* b     = (const float*)d_in[3];
    const float* gamma = (const float*)d_in[4];
    const float* beta  = (const float*)d_in[5];
    float* out = (float*)d_out;

    cudaFuncSetAttribute(mgemm_kernel,
                         cudaFuncAttributeMaxDynamicSharedMemorySize, SMEM_M_TOTAL);

    dummy_kernel<<<1, 32>>>();                 // keeps ncu slot 3 on mgemm

    prep_kernel<<<64, 256>>>(W, b, A);

    dim3 gz(TT / 10, NB);                      // (30, 64)
    zgemm_kernel<<<gz, 256>>>(x, A);

    dim3 gm(2 * MBLK, NB);                     // (118, 64): half in low bit
    mgemm_kernel<<<gm, 256, SMEM_M_TOTAL>>>(x, out);

    stats_kernel<<<CC, 256>>>(gamma, beta);

    normalize_kernel<<<2048, 256>>>(out, A, out_size);
}